// round 15
// baseline (speedup 1.0000x reference)
#include <cuda_runtime.h>
#include <math.h>

#define BATCH   64
#define VDIM    16384
#define FDIM    32
#define NSPLIT  16
#define ROWS_PER_SPLIT (VDIM / NSPLIT)          // 1024
#define GROUPS_PER_SPLIT (ROWS_PER_SPLIT / 4)   // 256 (4-row groups)

// Deterministic scratch (no float atomics): [B][NSPLIT][2][F]
__device__ float g_scratch[BATCH * NSPLIT * 2 * FDIM];
// Per-batch barrier counters (zero-init; self-reset each launch -> replay-safe)
__device__ int g_count[BATCH];
__device__ int g_done[BATCH];

// ---------------------------------------------------------------------------
// Fused kernel: reduce slice -> per-batch spin barrier -> rank -> permute the
// SAME slice (reverse order, L1/L2-hot) with LDG.128 / smem-permute / STG.128.
// 1024 blocks @ occupancy 8 => all resident => spin barrier is deadlock-free.
// ---------------------------------------------------------------------------
__global__ void __launch_bounds__(256, 8)
fused_kernel(const float4* __restrict__ fracs, const float2* __restrict__ feats,
             float4* __restrict__ out)
{
    const int b     = blockIdx.y;
    const int split = blockIdx.x;
    const int lane  = threadIdx.x & 31;
    const int warp  = threadIdx.x >> 5;
    const int q     = lane & 7;    // quad (4 columns) within row
    const int r     = lane >> 3;   // row within 4-row group

    const float4* __restrict__ fb = fracs + (size_t)b * VDIM * 8;  // 8 float4/row
    const float2* __restrict__ eb = feats + (size_t)b * VDIM * 2;
    const int g0 = split * GROUPS_PER_SPLIT;

    __shared__ float smS[8][FDIM];
    __shared__ float smW[8][FDIM];
    __shared__ int   s_perm[FDIM];
    __shared__ float stg[8][2][4][36];   // per-warp double-buffered 4x32 tile (+pad)

    // ================= Phase 1: reduce this slice (ascending) ===============
    float4 s  = make_float4(0.f, 0.f, 0.f, 0.f);
    float4 ws = make_float4(0.f, 0.f, 0.f, 0.f);

    #pragma unroll 4
    for (int g = warp; g < GROUPS_PER_SPLIT; g += 8) {
        const int v = (g0 + g) * 4 + r;
        float4 x  = __ldg(fb + (size_t)v * 8 + q);   // cache normally: re-read in phase 4
        float2 ee = __ldcs(eb + (size_t)v * 2);      // streamed once
        const float e  = ee.x;
        const float ew = ee.x * ee.y;
        s.x  += e  * x.x;  s.y  += e  * x.y;  s.z  += e  * x.z;  s.w  += e  * x.w;
        ws.x += ew * x.x;  ws.y += ew * x.y;  ws.z += ew * x.z;  ws.w += ew * x.w;
    }

    // fold the 4 row-groups (fixed order -> deterministic)
    #pragma unroll
    for (int off = 8; off <= 16; off <<= 1) {
        s.x  += __shfl_xor_sync(0xffffffffu, s.x,  off);
        s.y  += __shfl_xor_sync(0xffffffffu, s.y,  off);
        s.z  += __shfl_xor_sync(0xffffffffu, s.z,  off);
        s.w  += __shfl_xor_sync(0xffffffffu, s.w,  off);
        ws.x += __shfl_xor_sync(0xffffffffu, ws.x, off);
        ws.y += __shfl_xor_sync(0xffffffffu, ws.y, off);
        ws.z += __shfl_xor_sync(0xffffffffu, ws.z, off);
        ws.w += __shfl_xor_sync(0xffffffffu, ws.w, off);
    }
    if (r == 0) {
        *reinterpret_cast<float4*>(&smS[warp][q * 4]) = s;
        *reinterpret_cast<float4*>(&smW[warp][q * 4]) = ws;
    }
    __syncthreads();

    if (warp == 0) {
        float a = 0.f, wa = 0.f;
        #pragma unroll
        for (int w = 0; w < 8; w++) { a += smS[w][lane]; wa += smW[w][lane]; }
        float* dst = g_scratch + (size_t)(b * NSPLIT + split) * 2 * FDIM;
        dst[lane]        = a;
        dst[FDIM + lane] = wa;
    }
    __syncthreads();

    // ================= Phase 2: per-batch barrier ===========================
    if (threadIdx.x == 0) {
        __threadfence();                       // release scratch writes
        atomicAdd(&g_count[b], 1);
        while (*(volatile int*)&g_count[b] < NSPLIT) __nanosleep(64);
    }
    __syncthreads();

    // ================= Phase 3: weighted etas + stable rank =================
    if (warp == 0) {
        __threadfence();                       // acquire peers' scratch writes
        const int f = lane;
        float ts = 0.f, tws = 0.f;
        #pragma unroll
        for (int sp = 0; sp < NSPLIT; sp++) {
            const float* src = g_scratch + (size_t)(b * NSPLIT + sp) * 2 * FDIM;
            ts  += __ldcg(src + f);
            tws += __ldcg(src + FDIM + f);
        }
        float we = tws / (ts + 1e-7f);
        we = (fabsf(we) > 0.1f) ? we : 500.0f;

        // rank = #{j : we_j < we_f or (we_j == we_f and j < f)} (stable asc.)
        int rank = 0;
        #pragma unroll
        for (int j = 0; j < FDIM; j++) {
            float wj = __shfl_sync(0xffffffffu, we, j);
            rank += (int)((wj < we) || (wj == we && j < f));
        }
        s_perm[rank] = f;                      // forward perm: out col k <- src col perm[k]
    }
    __syncthreads();

    // ================= Phase 4: permute the SAME slice (descending) =========
    // source columns feeding this lane's contiguous output quad 4q..4q+3
    const int4 pk = *reinterpret_cast<const int4*>(&s_perm[4 * q]);
    float4* __restrict__ ob = out + (size_t)b * VDIM * 8;

    const int NITER = GROUPS_PER_SPLIT / 8;    // 32 iters per warp
    // iteration -> global element offset (reverse slice order: hottest first)
    #define ADDR(it) ((size_t)((g0 + (GROUPS_PER_SPLIT - 1 - (warp + (it) * 8))) * 4 + r) * 8 + q)

    float4 x0 = __ldg(fb + ADDR(0));
    float4 x1 = __ldg(fb + ADDR(1));

    for (int it = 0; it < NITER; ++it) {
        float4 xn;
        if (it + 2 < NITER) xn = __ldg(fb + ADDR(it + 2));   // depth-2 prefetch
        const int buf = it & 1;
        *reinterpret_cast<float4*>(&stg[warp][buf][r][4 * q]) = x0;
        __syncwarp();
        float4 y;
        y.x = stg[warp][buf][r][pk.x];
        y.y = stg[warp][buf][r][pk.y];
        y.z = stg[warp][buf][r][pk.z];
        y.w = stg[warp][buf][r][pk.w];
        __stcs(ob + ADDR(it), y);              // STG.128, full sectors, evict-first
        x0 = x1; x1 = xn;
    }
    #undef ADDR

    // ================= Phase 5: counter reset (replay safety) ===============
    __syncthreads();
    if (threadIdx.x == 0) {
        int d = atomicAdd(&g_done[b], 1);
        if (d == NSPLIT - 1) {                 // last finisher: everyone passed spin
            g_count[b] = 0;
            g_done[b]  = 0;
            __threadfence();
        }
    }
}

// ---------------------------------------------------------------------------
extern "C" void kernel_launch(void* const* d_in, const int* in_sizes, int n_in,
                              void* d_out, int out_size)
{
    const float4* fracs = (const float4*)d_in[0];   // [64,16384,32] f32
    const float2* feats = (const float2*)d_in[1];   // [64,16384,4]  f32
    float4*       out   = (float4*)d_out;           // [64,16384,32] f32

    dim3 grid(NSPLIT, BATCH);                        // 1024 blocks, all resident @occ8
    fused_kernel<<<grid, 256>>>(fracs, feats, out);
}

// round 16
// speedup vs baseline: 1.0492x; 1.0492x over previous
#include <cuda_runtime.h>
#include <math.h>

#define BATCH   64
#define VDIM    16384
#define FDIM    32
#define NSPLIT  16
#define ROWS_PER_SPLIT (VDIM / NSPLIT)          // 1024
#define GROUPS_PER_SPLIT (ROWS_PER_SPLIT / 4)   // 256 (4-row groups)
#define NGROUPS (VDIM / 4)                       // 4096 per batch

// Deterministic scratch (no float atomics): [B][NSPLIT][2][F]
__device__ float g_scratch[BATCH * NSPLIT * 2 * FDIM];

// ---------------------------------------------------------------------------
// Pass 1: split reduction, software-pipelined depth-4 prefetch.
// Lane l: row-in-group r = l/8, quad q = l%8 (columns 4q..4q+3).
// Warp iterates 32 groups (GROUPS_PER_SPLIT/8); both streams prefetched so
// ~10 loads are in flight per warp at all times.
// ---------------------------------------------------------------------------
__global__ void __launch_bounds__(256)
reduce_kernel(const float4* __restrict__ fracs, const float2* __restrict__ feats)
{
    const int b     = blockIdx.y;
    const int split = blockIdx.x;
    const int lane  = threadIdx.x & 31;
    const int warp  = threadIdx.x >> 5;
    const int q     = lane & 7;
    const int r     = lane >> 3;

    const float4* __restrict__ fb = fracs + (size_t)b * VDIM * 8;  // 8 float4/row
    const float2* __restrict__ eb = feats + (size_t)b * VDIM * 2;  // 2 float2/row
    const int g0 = split * GROUPS_PER_SPLIT;

    const int NITER = GROUPS_PER_SPLIT / 8;    // 32 iterations per warp
    #define VROW(it)  ((g0 + warp + (it) * 8) * 4 + r)

    float4 s  = make_float4(0.f, 0.f, 0.f, 0.f);
    float4 ws = make_float4(0.f, 0.f, 0.f, 0.f);

    // depth-4 software pipeline
    float4 xb[4];
    float2 fbuf[4];
    #pragma unroll
    for (int p = 0; p < 4; p++) {
        xb[p]   = __ldcs(fb + (size_t)VROW(p) * 8 + q);
        fbuf[p] = __ldcs(eb + (size_t)VROW(p) * 2);
    }

    #pragma unroll 4
    for (int it = 0; it < NITER; ++it) {
        const int p = it & 3;
        float4 x  = xb[p];
        float2 ee = fbuf[p];
        if (it + 4 < NITER) {
            xb[p]   = __ldcs(fb + (size_t)VROW(it + 4) * 8 + q);
            fbuf[p] = __ldcs(eb + (size_t)VROW(it + 4) * 2);
        }
        const float e  = ee.x;
        const float ew = ee.x * ee.y;
        s.x  += e  * x.x;  s.y  += e  * x.y;  s.z  += e  * x.z;  s.w  += e  * x.w;
        ws.x += ew * x.x;  ws.y += ew * x.y;  ws.z += ew * x.z;  ws.w += ew * x.w;
    }
    #undef VROW

    // fold the 4 row-groups: xor-shuffle over lane bits 3,4 (fixed order).
    #pragma unroll
    for (int off = 8; off <= 16; off <<= 1) {
        s.x  += __shfl_xor_sync(0xffffffffu, s.x,  off);
        s.y  += __shfl_xor_sync(0xffffffffu, s.y,  off);
        s.z  += __shfl_xor_sync(0xffffffffu, s.z,  off);
        s.w  += __shfl_xor_sync(0xffffffffu, s.w,  off);
        ws.x += __shfl_xor_sync(0xffffffffu, ws.x, off);
        ws.y += __shfl_xor_sync(0xffffffffu, ws.y, off);
        ws.z += __shfl_xor_sync(0xffffffffu, ws.z, off);
        ws.w += __shfl_xor_sync(0xffffffffu, ws.w, off);
    }

    __shared__ float smS[8][FDIM];
    __shared__ float smW[8][FDIM];
    if (r == 0) {                    // lanes 0..7 hold totals for quad q
        *reinterpret_cast<float4*>(&smS[warp][q * 4]) = s;
        *reinterpret_cast<float4*>(&smW[warp][q * 4]) = ws;
    }
    __syncthreads();

    if (warp == 0) {
        float a = 0.f, wa = 0.f;
        #pragma unroll
        for (int w = 0; w < 8; w++) {
            a  += smS[w][lane];
            wa += smW[w][lane];
        }
        float* dst = g_scratch + (size_t)(b * NSPLIT + split) * 2 * FDIM;
        dst[lane]        = a;
        dst[FDIM + lane] = wa;
    }
}

// ---------------------------------------------------------------------------
// Pass 2 (fused sort + permute):
//  - warp 0 computes weighted etas (fixed split order -> deterministic) and
//    the stable counting-rank matching jax.lax.top_k(-we) tie semantics;
//    stores the FORWARD permutation: out col k <- src col perm[k].
//  - all warps permute via smem tile: LDG.128 -> STS.128 -> 4x LDS.32
//    (register-resident perm) -> STG.128 of contiguous output columns.
//    Depth-2 read prefetch keeps load MLP across the __syncwarp.
// ---------------------------------------------------------------------------
__global__ void __launch_bounds__(256)
gather_kernel(const float4* __restrict__ fracs, float4* __restrict__ out)
{
    __shared__ int   s_perm[FDIM];
    __shared__ float stg[8][2][4][36];   // per-warp double-buffered 4x32 tile (+pad)

    const int b = blockIdx.y;

    if (threadIdx.x < 32) {
        const int f = threadIdx.x;
        float s = 0.f, ws = 0.f;
        #pragma unroll
        for (int sp = 0; sp < NSPLIT; sp++) {
            const float* src = g_scratch + (size_t)(b * NSPLIT + sp) * 2 * FDIM;
            s  += src[f];
            ws += src[FDIM + f];
        }
        float we = ws / (s + 1e-7f);
        we = (fabsf(we) > 0.1f) ? we : 500.0f;

        // rank = #{j : we_j < we_f or (we_j == we_f and j < f)} (stable asc.)
        int rank = 0;
        #pragma unroll
        for (int j = 0; j < FDIM; j++) {
            float wj = __shfl_sync(0xffffffffu, we, j);
            rank += (int)((wj < we) || (wj == we && j < f));
        }
        s_perm[rank] = f;                // forward perm
    }
    __syncthreads();

    const int lane = threadIdx.x & 31;
    const int warp = threadIdx.x >> 5;
    const int q    = lane & 7;
    const int r    = lane >> 3;
    const int wi   = blockIdx.x * 8 + warp;
    const int nw   = gridDim.x * 8;      // 144 warps... (18*8)

    // source columns feeding this lane's contiguous output quad 4q..4q+3
    const int4 pk = *reinterpret_cast<const int4*>(&s_perm[4 * q]);

    const float4* __restrict__ src = fracs + (size_t)b * VDIM * 8;
    float4*       __restrict__ dst = out   + (size_t)b * VDIM * 8;

    // warp processes groups wi, wi+nw, ... ascending; depth-2 prefetch
    #define GADDR(g) ((size_t)((g) * 4 + r) * 8 + q)

    int g_cur = wi;
    float4 x0, x1;
    if (g_cur < NGROUPS)       x0 = __ldcs(src + GADDR(g_cur));
    if (g_cur + nw < NGROUPS)  x1 = __ldcs(src + GADDR(g_cur + nw));

    for (; g_cur < NGROUPS; g_cur += nw) {
        float4 xn;
        if (g_cur + 2 * nw < NGROUPS) xn = __ldcs(src + GADDR(g_cur + 2 * nw));
        const int buf = (g_cur / nw) & 1;
        *reinterpret_cast<float4*>(&stg[warp][buf][r][4 * q]) = x0;
        __syncwarp();
        float4 y;
        y.x = stg[warp][buf][r][pk.x];
        y.y = stg[warp][buf][r][pk.y];
        y.z = stg[warp][buf][r][pk.z];
        y.w = stg[warp][buf][r][pk.w];
        __stcs(dst + GADDR(g_cur), y);   // STG.128, fully coalesced
        x0 = x1; x1 = xn;
    }
    #undef GADDR
}

// ---------------------------------------------------------------------------
extern "C" void kernel_launch(void* const* d_in, const int* in_sizes, int n_in,
                              void* d_out, int out_size)
{
    const float4* fracs = (const float4*)d_in[0];   // [64,16384,32] f32
    const float2* feats = (const float2*)d_in[1];   // [64,16384,4]  f32
    float4*       out   = (float4*)d_out;           // [64,16384,32] f32

    dim3 g1(NSPLIT, BATCH);    // 1024 blocks — single wave
    reduce_kernel<<<g1, 256>>>(fracs, feats);

    dim3 g2(18, BATCH);        // 1152 blocks — single wave
    gather_kernel<<<g2, 256>>>(fracs, out);
}